// round 2
// baseline (speedup 1.0000x reference)
#include <cuda_runtime.h>

// ---------------------------------------------------------------------------
// CubicHermite2d — separable 2-pass cubic Hermite interpolation, evaluated
// with the LITERAL reference formula (no weight folding):
//   result = h00*y[I] + h10*m[I] + h01*y[I+1] + h11*m[I+1]      (dx = 1)
//   m[0] = y1-y0; m[N-1] = y[N-1]-y[N-2]; m[i] = 0.5*(y[i+1]-y[i-1])
// Bucket index matches searchsorted(x0[1:-1], v, 'left') exactly:
//   I = clamp(ceil(v)-1, 0, N-2)
// ---------------------------------------------------------------------------

#define MAXQ 4096
#define TMP_ELEMS (32u * 512u * 1024u)   // B*H*Nx intermediate [B, H, Nx]

__device__ int    g_ix[MAXQ];
__device__ float4 g_hx[MAXQ];   // (h00, h10, h01, h11)
__device__ int    g_iy[MAXQ];
__device__ float4 g_hy[MAXQ];
__device__ float  g_tmp[TMP_ELEMS];

__device__ __forceinline__ void hermite_h(float v, int N, int* Iout, float4* hout) {
    int I = (int)ceilf(v) - 1;          // == searchsorted(x0[1:-1], v, 'left')
    I = max(0, min(I, N - 2));
    float t  = v - (float)I;
    float t2 = t * t;
    float t3 = t2 * t;
    *Iout = I;
    *hout = make_float4(1.0f - 3.0f * t2 + 2.0f * t3,   // h00
                        t - 2.0f * t2 + t3,             // h10
                        3.0f * t2 - 2.0f * t3,          // h01
                        t3 - t2);                       // h11
}

__global__ void k_weights(const float* __restrict__ xs, int Nqx, int Wn,
                          const float* __restrict__ ys, int Nqy, int Hn) {
    if (blockIdx.x == 0) {
        for (int q = threadIdx.x; q < Nqx; q += blockDim.x)
            hermite_h(xs[q], Wn, &g_ix[q], &g_hx[q]);
    } else {
        for (int q = threadIdx.x; q < Nqy; q += blockDim.x)
            hermite_h(ys[q], Hn, &g_iy[q], &g_hy[q]);
    }
}

// Pass 1: one block per (b,h) row; the W-float row lives in smem.
__global__ void k_pass1(const float* __restrict__ sig, int W, int Nx) {
    __shared__ float s[2048];
    long long row = blockIdx.x;
    const float* rp = sig + row * (long long)W;
    for (int i = threadIdx.x; i < W; i += blockDim.x) s[i] = rp[i];
    __syncthreads();

    float* op = g_tmp + row * (long long)Nx;
    for (int q = threadIdx.x; q < Nx; q += blockDim.x) {
        int    I = g_ix[q];
        float4 h = g_hx[q];
        float ylo = s[I];
        float yhi = s[I + 1];
        float mlo = (I == 0)     ? (s[1] - s[0])
                                 : 0.5f * (s[I + 1] - s[I - 1]);
        float mhi = (I == W - 2) ? (s[W - 1] - s[W - 2])
                                 : 0.5f * (s[I + 2] - s[I]);
        op[q] = h.x * ylo + h.y * mlo + h.z * yhi + h.w * mhi;
    }
}

// Pass 2: out[b][qy][qx], float4 along qx; 4 tmp rows per output row.
__global__ void k_pass2(float* __restrict__ out, int H, int Nx, int Ny) {
    int nx4 = Nx >> 2;
    int qx4 = blockIdx.x * blockDim.x + threadIdx.x;
    if (qx4 >= nx4) return;
    int qy = blockIdx.y;
    int b  = blockIdx.z;

    int    I = g_iy[qy];
    float4 h = g_hy[qy];

    const float4* tp = reinterpret_cast<const float4*>(g_tmp + (size_t)b * H * Nx) + qx4;
    float4 r1 = tp[(size_t)I * nx4];                       // y[I]
    float4 r2 = tp[(size_t)(I + 1) * nx4];                 // y[I+1]
    float4 r0 = tp[(size_t)max(I - 1, 0) * nx4];           // y[I-1] (unused if I==0)
    float4 r3 = tp[(size_t)min(I + 2, H - 1) * nx4];       // y[I+2] (unused if I==H-2)

    bool lo_edge = (I == 0);
    bool hi_edge = (I == H - 2);

    float4 o;
    {
        float mlo = lo_edge ? (r2.x - r1.x) : 0.5f * (r2.x - r0.x);
        float mhi = hi_edge ? (r2.x - r1.x) : 0.5f * (r3.x - r1.x);
        o.x = h.x * r1.x + h.y * mlo + h.z * r2.x + h.w * mhi;
    }
    {
        float mlo = lo_edge ? (r2.y - r1.y) : 0.5f * (r2.y - r0.y);
        float mhi = hi_edge ? (r2.y - r1.y) : 0.5f * (r3.y - r1.y);
        o.y = h.x * r1.y + h.y * mlo + h.z * r2.y + h.w * mhi;
    }
    {
        float mlo = lo_edge ? (r2.z - r1.z) : 0.5f * (r2.z - r0.z);
        float mhi = hi_edge ? (r2.z - r1.z) : 0.5f * (r3.z - r1.z);
        o.z = h.x * r1.z + h.y * mlo + h.z * r2.z + h.w * mhi;
    }
    {
        float mlo = lo_edge ? (r2.w - r1.w) : 0.5f * (r2.w - r0.w);
        float mhi = hi_edge ? (r2.w - r1.w) : 0.5f * (r3.w - r1.w);
        o.w = h.x * r1.w + h.y * mlo + h.z * r2.w + h.w * mhi;
    }

    reinterpret_cast<float4*>(out)[((size_t)b * Ny + qy) * nx4 + qx4] = o;
}

extern "C" void kernel_launch(void* const* d_in, const int* in_sizes, int n_in,
                              void* d_out, int out_size) {
    const float* sig = (const float*)d_in[0];
    // d_in[1] = x1 (arange, dx=1), d_in[2] = x2 (arange, dx=1)
    const float* xs  = (const float*)d_in[3];
    const float* ys  = (const float*)d_in[4];

    int W  = in_sizes[1];
    int H  = in_sizes[2];
    int Nx = in_sizes[3];
    int Ny = in_sizes[4];
    int B  = in_sizes[0] / (W * H);

    k_weights<<<2, 1024>>>(xs, Nx, W, ys, Ny, H);
    k_pass1<<<B * H, 512>>>(sig, W, Nx);

    dim3 g2((Nx / 4 + 255) / 256, Ny, B);
    k_pass2<<<g2, 256>>>((float*)d_out, H, Nx, Ny);
}